// round 15
// baseline (speedup 1.0000x reference)
#include <cuda_runtime.h>
#include <cuda_bf16.h>
#include <cstdint>

#define KN      100000
#define KE      1600000
#define KIN     256
#define KED     64
#define KH      4
#define KC      32
#define KHC     128

#define FULLM 0xFFFFFFFFu

// ---------------- scratch (static device globals; no allocation) ----------------
__device__ float4 g_xproj[KN * 32];        // [N][128]  (51.2 MB)
__device__ float4 g_asrc[KN];
__device__ float4 g_adst[KN];
__device__ float  g_W2[KED * KH];          // [64][4]
__device__ float  g_loopsum[KH];
__device__ int    g_deg[KN];
__device__ int    g_off[KN + 1];
__device__ int    g_cursor[KN];
__device__ int    g_bsum[512];
__device__ int    g_boff[512];
__device__ int    g_ssrc[KE];
__device__ float4 g_salpha[KE];            // (25.6 MB)

// ---------------- reset ----------------
__global__ void k_reset(int n) {
    int i = blockIdx.x * blockDim.x + threadIdx.x;
    if (i < n) g_deg[i] = 0;
    if (i < KH) g_loopsum[i] = 0.f;
}

// ---------------- W2[d][h] = sum_c W_edge[d, h*32+c] * att_edge[h, c] ----------------
__global__ void k_w2(const float* __restrict__ W_edge, const float* __restrict__ att_edge) {
    int t = threadIdx.x;                 // 256 threads
    int d = t >> 2, h = t & 3;
    float s = 0.f;
    #pragma unroll 8
    for (int c = 0; c < KC; c++)
        s += W_edge[d * KHC + h * KC + c] * att_edge[h * KC + c];
    g_W2[d * KH + h] = s;
}

// ---------------- histogram of dst ----------------
__global__ void k_hist(const int* __restrict__ edge_index, int E) {
    int e = blockIdx.x * blockDim.x + threadIdx.x;
    if (e < E) atomicAdd(&g_deg[edge_index[E + e]], 1);
}

// ---------------- GEMM: 512 threads, 8x4 microtile, 16 warps/SM ----------------
__global__ __launch_bounds__(512) void k_gemm(const float* __restrict__ x,
                                              const float* __restrict__ W, int n) {
    __shared__ float Xs[2][16][128];
    __shared__ float Ws[2][16][128];
    int tid = threadIdx.x;
    int bm = blockIdx.x * 128;
    int tx = tid & 31;           // 0..31 -> 4-col group
    int ty = tid >> 5;           // 0..15 -> 8-row group

    float acc[8][4];
    #pragma unroll
    for (int i = 0; i < 8; i++)
        #pragma unroll
        for (int j = 0; j < 4; j++) acc[i][j] = 0.f;

    // load tasks: X row = tid>>2 (0..127), k-quad = tid&3 ; W k = tid>>5, col4 = (tid&31)*4
    int xr = tid >> 2;
    int xk = (tid & 3) << 2;
    int wk = tid >> 5;
    int wn = (tid & 31) << 2;

    int gm0 = bm + xr;
    const float* xrow0 = x + (size_t)(gm0 < n ? gm0 : 0) * KIN + xk;
    bool v0 = gm0 < n;
    const float* wrow0 = W + (size_t)wk * KHC + wn;
    const float4 z4 = make_float4(0.f, 0.f, 0.f, 0.f);

    float4 xv0 = v0 ? *(const float4*)(xrow0) : z4;
    float4 wv0 = *(const float4*)(wrow0);

    #pragma unroll 1
    for (int c = 0; c < 16; c++) {
        int s = c & 1;
        Xs[s][xk + 0][xr] = xv0.x;
        Xs[s][xk + 1][xr] = xv0.y;
        Xs[s][xk + 2][xr] = xv0.z;
        Xs[s][xk + 3][xr] = xv0.w;
        *(float4*)&Ws[s][wk][wn] = wv0;
        __syncthreads();
        if (c < 15) {
            int kb = (c + 1) * 16;
            xv0 = v0 ? *(const float4*)(xrow0 + kb) : z4;
            wv0 = *(const float4*)(wrow0 + (size_t)kb * KHC);
        }
        #pragma unroll
        for (int k = 0; k < 16; k++) {
            float4 a0 = *(const float4*)&Xs[s][k][ty * 8];
            float4 a1 = *(const float4*)&Xs[s][k][ty * 8 + 4];
            float4 b0 = *(const float4*)&Ws[s][k][tx * 4];
            float av[8] = {a0.x, a0.y, a0.z, a0.w, a1.x, a1.y, a1.z, a1.w};
            #pragma unroll
            for (int i = 0; i < 8; i++) {
                acc[i][0] += av[i] * b0.x;
                acc[i][1] += av[i] * b0.y;
                acc[i][2] += av[i] * b0.z;
                acc[i][3] += av[i] * b0.w;
            }
        }
        __syncthreads();
    }
    #pragma unroll
    for (int i = 0; i < 8; i++) {
        int gm = bm + ty * 8 + i;
        if (gm < n)
            g_xproj[(size_t)gm * 32 + tx] =
                make_float4(acc[i][0], acc[i][1], acc[i][2], acc[i][3]);
    }
}

// ---------------- a_src / a_dst: warp per node ----------------
__global__ void k_attn(const float* __restrict__ att_src,
                       const float* __restrict__ att_dst, int n) {
    int warp = (blockIdx.x * blockDim.x + threadIdx.x) >> 5;
    int lane = threadIdx.x & 31;
    if (warp >= n) return;
    float4 xp = g_xproj[(size_t)warp * 32 + lane];
    float4 as = *(const float4*)(att_src + lane * 4);
    float4 ad = *(const float4*)(att_dst + lane * 4);
    float ds = xp.x * as.x + xp.y * as.y + xp.z * as.z + xp.w * as.w;
    float dd = xp.x * ad.x + xp.y * ad.y + xp.z * ad.z + xp.w * ad.w;
    #pragma unroll
    for (int m = 1; m <= 4; m <<= 1) {
        ds += __shfl_xor_sync(FULLM, ds, m);
        dd += __shfl_xor_sync(FULLM, dd, m);
    }
    if ((lane & 7) == 0) {
        int h = lane >> 3;
        ((float*)&g_asrc[warp])[h] = ds;
        ((float*)&g_adst[warp])[h] = dd;
    }
}

// ---------------- 3-stage chip-wide exclusive scan of g_deg ----------------
__global__ void k_scan1(int n) {
    __shared__ int s[256];
    int t = threadIdx.x;
    int i = blockIdx.x * 256 + t;
    int v = (i < n) ? g_deg[i] : 0;
    s[t] = v;
    __syncthreads();
    #pragma unroll
    for (int o = 128; o > 0; o >>= 1) {
        if (t < o) s[t] += s[t + o];
        __syncthreads();
    }
    if (t == 0) g_bsum[blockIdx.x] = s[0];
}

__global__ void k_scan2(int nb, int n) {
    __shared__ int s[512];
    int t = threadIdx.x;
    int v = (t < nb) ? g_bsum[t] : 0;
    s[t] = v;
    __syncthreads();
    #pragma unroll
    for (int o = 1; o < 512; o <<= 1) {
        int u = (t >= o) ? s[t - o] : 0;
        __syncthreads();
        s[t] += u;
        __syncthreads();
    }
    if (t < nb) g_boff[t] = s[t] - v;
    if (t == 511) g_off[n] = s[511];
}

__global__ void k_scan3(int n) {
    __shared__ int s[256];
    int t = threadIdx.x;
    int i = blockIdx.x * 256 + t;
    int v = (i < n) ? g_deg[i] : 0;
    s[t] = v;
    __syncthreads();
    #pragma unroll
    for (int o = 1; o < 256; o <<= 1) {
        int u = (t >= o) ? s[t - o] : 0;
        __syncthreads();
        s[t] += u;
        __syncthreads();
    }
    if (i < n) {
        int off = g_boff[blockIdx.x] + s[t] - v;
        g_off[i] = off;
        g_cursor[i] = off;
    }
}

// ---------------- fused escore + scatter: 32 edges/warp, two-phase ----------------
__global__ __launch_bounds__(256) void k_scatf(const int* __restrict__ edge_index,
                                               const float* __restrict__ edge_attr, int E) {
    __shared__ float Ws2[KED * KH];
    __shared__ float bp[KH];
    __shared__ float4 sp[8][32];            // [warp][edge-in-chunk] p-vector
    int tid = threadIdx.x;
    Ws2[tid] = g_W2[tid];
    if (tid < KH) bp[tid] = 0.f;
    __syncthreads();

    int lane = tid & 31, wid = tid >> 5;
    int l8 = lane & 7, g8 = lane >> 3;

    float wr[8][4];
    #pragma unroll
    for (int j = 0; j < 8; j++)
        #pragma unroll
        for (int h = 0; h < 4; h++)
            wr[j][h] = Ws2[(l8 * 8 + j) * 4 + h];

    float s0 = 0.f, s1 = 0.f, s2 = 0.f, s3 = 0.f;
    int nchunks = (E + 31) >> 5;
    int cw = gridDim.x * 8;

    for (int c = blockIdx.x * 8 + wid; c < nchunks; c += cw) {
        int e0 = c * 32;
        float4 va[8], vb[8];
        #pragma unroll
        for (int j = 0; j < 8; j++) {
            int e = e0 + j * 4 + g8;
            const float* ea = edge_attr + (size_t)(e < E ? e : 0) * KED + l8 * 8;
            va[j] = *(const float4*)ea;
            vb[j] = *(const float4*)(ea + 4);
        }
        #pragma unroll
        for (int j = 0; j < 8; j++) {
            float av[8] = {va[j].x, va[j].y, va[j].z, va[j].w,
                           vb[j].x, vb[j].y, vb[j].z, vb[j].w};
            float p0 = 0.f, p1 = 0.f, p2 = 0.f, p3 = 0.f;
            #pragma unroll
            for (int q = 0; q < 8; q++) {
                p0 += av[q] * wr[q][0];
                p1 += av[q] * wr[q][1];
                p2 += av[q] * wr[q][2];
                p3 += av[q] * wr[q][3];
            }
            #pragma unroll
            for (int m = 1; m <= 4; m <<= 1) {
                p0 += __shfl_xor_sync(FULLM, p0, m);
                p1 += __shfl_xor_sync(FULLM, p1, m);
                p2 += __shfl_xor_sync(FULLM, p2, m);
                p3 += __shfl_xor_sync(FULLM, p3, m);
            }
            if (l8 == 0) {
                sp[wid][j * 4 + g8] = make_float4(p0, p1, p2, p3);
                if (e0 + j * 4 + g8 < E) { s0 += p0; s1 += p1; s2 += p2; s3 += p3; }
            }
        }
        __syncwarp();
        int e = e0 + lane;
        if (e < E) {
            float4 p = sp[wid][lane];
            int src = edge_index[e];
            int dst = edge_index[E + e];
            float4 as = g_asrc[src];
            int pos = atomicAdd(&g_cursor[dst], 1);
            g_ssrc[pos] = src;
            g_salpha[pos] = make_float4(as.x + p.x, as.y + p.y, as.z + p.z, as.w + p.w);
        }
        __syncwarp();
    }
    #pragma unroll
    for (int m = 8; m <= 16; m <<= 1) {
        s0 += __shfl_xor_sync(FULLM, s0, m);
        s1 += __shfl_xor_sync(FULLM, s1, m);
        s2 += __shfl_xor_sync(FULLM, s2, m);
        s3 += __shfl_xor_sync(FULLM, s3, m);
    }
    if (lane == 0) {
        atomicAdd(&bp[0], s0);
        atomicAdd(&bp[1], s1);
        atomicAdd(&bp[2], s2);
        atomicAdd(&bp[3], s3);
    }
    __syncthreads();
    if (tid < KH) atomicAdd(&g_loopsum[tid], bp[tid]);
}

// ---------------- aggregation: warp per node, prefetched softmax + weighted sum ----------------
__global__ __launch_bounds__(256) void k_agg(const float* __restrict__ bias,
                                             float* __restrict__ out, int n, float invE) {
    int i = (blockIdx.x * blockDim.x + threadIdx.x) >> 5;
    int lane = threadIdx.x & 31;
    if (i >= n) return;

    int hl = lane >> 3;
    int sub = lane & 3;

    float adst_s = ((const float*)&g_adst[i])[sub];
    float asrc_s = ((const float*)&g_asrc[i])[sub];
    float lae_s  = g_loopsum[sub] * invE;
    float4 xpi = g_xproj[(size_t)i * 32 + lane];

    float4 acc = make_float4(0.f, 0.f, 0.f, 0.f);
    float dsum = 0.f;

    float vs = asrc_s + adst_s + lae_s;
    vs = vs > 0.f ? vs : 0.2f * vs;
    float ws = __expf(vs);
    if (lane < 4) dsum += ws;
    {
        float w = __shfl_sync(FULLM, ws, hl);
        acc.x += w * xpi.x; acc.y += w * xpi.y; acc.z += w * xpi.z; acc.w += w * xpi.w;
    }

    int beg = g_off[i], end = g_off[i + 1];
    const float* salpha_f = (const float*)g_salpha;

    float ca = 0.f; int cs = i;
    if (beg < end) {
        if (beg + (lane >> 2) < end) ca = salpha_f[(size_t)beg * 4 + lane];
        if (lane < 8 && beg + lane < end) cs = g_ssrc[beg + lane];
    }
    for (int base = beg; base < end; base += 8) {
        int nb = base + 8;
        float na = 0.f; int ns = i;
        if (nb < end) {
            if (nb + (lane >> 2) < end) na = salpha_f[(size_t)nb * 4 + lane];
            if (lane < 8 && nb + lane < end) ns = g_ssrc[nb + lane];
        }
        float w = 0.f;
        if (base + (lane >> 2) < end) {
            float a = ca + adst_s;
            a = a > 0.f ? a : 0.2f * a;
            w = __expf(a);
        }
        dsum += w;
        #pragma unroll
        for (int k = 0; k < 8; k++) {
            int s = __shfl_sync(FULLM, cs, k);
            float we = __shfl_sync(FULLM, w, k * 4 + hl);
            float4 xp = g_xproj[(size_t)s * 32 + lane];
            acc.x += we * xp.x; acc.y += we * xp.y;
            acc.z += we * xp.z; acc.w += we * xp.w;
        }
        ca = na; cs = ns;
    }
    #pragma unroll
    for (int m = 4; m <= 16; m <<= 1) dsum += __shfl_xor_sync(FULLM, dsum, m);
    float denom = __shfl_sync(FULLM, dsum, hl);
    float inv = 1.0f / denom;
    float4 b4 = *(const float4*)(bias + lane * 4);
    float4 o;
    o.x = acc.x * inv + b4.x;
    o.y = acc.y * inv + b4.y;
    o.z = acc.z * inv + b4.z;
    o.w = acc.w * inv + b4.w;
    *(float4*)(out + (size_t)i * KHC + lane * 4) = o;
}

// ---------------- launch (k_gemm-512 at #4 for ncu capture) ----------------
extern "C" void kernel_launch(void* const* d_in, const int* in_sizes, int n_in,
                              void* d_out, int out_size) {
    const float* x         = (const float*)d_in[0];
    const int*   edge_idx  = (const int*)d_in[1];
    const float* edge_attr = (const float*)d_in[2];
    const float* W         = (const float*)d_in[3];
    const float* att_src   = (const float*)d_in[4];
    const float* att_dst   = (const float*)d_in[5];
    const float* W_edge    = (const float*)d_in[6];
    const float* att_edge  = (const float*)d_in[7];
    const float* bias      = (const float*)d_in[8];
    float* out = (float*)d_out;

    int n = in_sizes[0] / KIN;       // 100000
    int E = in_sizes[1] / 2;         // 1600000
    int nblk = (n + 255) / 256;      // 391

    k_reset<<<nblk, 256>>>(n);
    k_hist<<<(E + 255) / 256, 256>>>(edge_idx, E);
    k_w2<<<1, 256>>>(W_edge, att_edge);
    k_gemm<<<(n + 127) / 128, 512>>>(x, W, n);       // #4 -> profiled
    k_attn<<<(n + 7) / 8, 256>>>(att_src, att_dst, n);
    k_scan1<<<nblk, 256>>>(n);
    k_scan2<<<1, 512>>>(nblk, n);
    k_scan3<<<nblk, 256>>>(n);
    k_scatf<<<2048, 256>>>(edge_idx, edge_attr, E);
    k_agg<<<(n + 7) / 8, 256>>>(bias, out, n, 1.0f / (float)E);
}

// round 16
// speedup vs baseline: 1.1388x; 1.1388x over previous
#include <cuda_runtime.h>
#include <cuda_bf16.h>
#include <cstdint>

#define KN      100000
#define KE      1600000
#define KIN     256
#define KED     64
#define KH      4
#define KC      32
#define KHC     128

#define FULLM 0xFFFFFFFFu

// ---------------- scratch (static device globals; no allocation) ----------------
__device__ float4 g_xproj[KN * 32];        // [N][128]  (51.2 MB)
__device__ float4 g_asrc[KN];
__device__ float4 g_adst[KN];
__device__ float  g_W2[KED * KH];          // [64][4]
__device__ float  g_loopsum[KH];
__device__ int    g_deg[KN];
__device__ int    g_off[KN + 1];
__device__ int    g_cursor[KN];
__device__ int    g_bsum[512];
__device__ int    g_boff[512];
__device__ int    g_ssrc[KE];
__device__ float4 g_salpha[KE];            // (25.6 MB)

// ---------------- reset ----------------
__global__ void k_reset(int n) {
    int i = blockIdx.x * blockDim.x + threadIdx.x;
    if (i < n) g_deg[i] = 0;
    if (i < KH) g_loopsum[i] = 0.f;
}

// ---------------- W2[d][h] = sum_c W_edge[d, h*32+c] * att_edge[h, c] ----------------
__global__ void k_w2(const float* __restrict__ W_edge, const float* __restrict__ att_edge) {
    int t = threadIdx.x;                 // 256 threads
    int d = t >> 2, h = t & 3;
    float s = 0.f;
    #pragma unroll 8
    for (int c = 0; c < KC; c++)
        s += W_edge[d * KHC + h * KC + c] * att_edge[h * KC + c];
    g_W2[d * KH + h] = s;
}

// ---------------- histogram of dst ----------------
__global__ void k_hist(const int* __restrict__ edge_index, int E) {
    int e = blockIdx.x * blockDim.x + threadIdx.x;
    if (e < E) atomicAdd(&g_deg[edge_index[E + e]], 1);
}

// ---------------- GEMM: x_proj = x[N,256] @ W[256,128]  (EXACT r14/r8 kernel) ----------------
__global__ __launch_bounds__(256) void k_gemm(const float* __restrict__ x,
                                              const float* __restrict__ W, int n) {
    __shared__ float Xs[2][16][128];
    __shared__ float Ws[2][16][128];
    int tid = threadIdx.x;
    int bm = blockIdx.x * 128;
    int tx = tid & 15;
    int ty = tid >> 4;

    float acc[8][8];
    #pragma unroll
    for (int i = 0; i < 8; i++)
        #pragma unroll
        for (int j = 0; j < 8; j++) acc[i][j] = 0.f;

    int xr = tid >> 2;
    int xk = (tid & 3) << 2;
    int wk = tid >> 5;
    int wn = (tid & 31) << 2;

    int gm0 = bm + xr;
    int gm1 = bm + xr + 64;
    const float* xrow0 = x + (size_t)(gm0 < n ? gm0 : 0) * KIN + xk;
    const float* xrow1 = x + (size_t)(gm1 < n ? gm1 : 0) * KIN + xk;
    bool v0 = gm0 < n, v1 = gm1 < n;
    const float* wrow0 = W + (size_t)wk * KHC + wn;
    const float* wrow1 = W + (size_t)(wk + 8) * KHC + wn;
    const float4 z4 = make_float4(0.f, 0.f, 0.f, 0.f);

    float4 xv0 = v0 ? *(const float4*)(xrow0) : z4;
    float4 xv1 = v1 ? *(const float4*)(xrow1) : z4;
    float4 wv0 = *(const float4*)(wrow0);
    float4 wv1 = *(const float4*)(wrow1);

    #pragma unroll 1
    for (int c = 0; c < 16; c++) {
        int s = c & 1;
        Xs[s][xk + 0][xr] = xv0.x;
        Xs[s][xk + 1][xr] = xv0.y;
        Xs[s][xk + 2][xr] = xv0.z;
        Xs[s][xk + 3][xr] = xv0.w;
        Xs[s][xk + 0][xr + 64] = xv1.x;
        Xs[s][xk + 1][xr + 64] = xv1.y;
        Xs[s][xk + 2][xr + 64] = xv1.z;
        Xs[s][xk + 3][xr + 64] = xv1.w;
        *(float4*)&Ws[s][wk][wn] = wv0;
        *(float4*)&Ws[s][wk + 8][wn] = wv1;
        __syncthreads();
        if (c < 15) {
            int kb = (c + 1) * 16;
            xv0 = v0 ? *(const float4*)(xrow0 + kb) : z4;
            xv1 = v1 ? *(const float4*)(xrow1 + kb) : z4;
            wv0 = *(const float4*)(wrow0 + (size_t)kb * KHC);
            wv1 = *(const float4*)(wrow1 + (size_t)kb * KHC);
        }
        #pragma unroll
        for (int k = 0; k < 16; k++) {
            float4 a0 = *(const float4*)&Xs[s][k][ty * 8];
            float4 a1 = *(const float4*)&Xs[s][k][ty * 8 + 4];
            float4 b0 = *(const float4*)&Ws[s][k][tx * 4];
            float4 b1 = *(const float4*)&Ws[s][k][tx * 4 + 64];
            float av[8] = {a0.x, a0.y, a0.z, a0.w, a1.x, a1.y, a1.z, a1.w};
            float bv[8] = {b0.x, b0.y, b0.z, b0.w, b1.x, b1.y, b1.z, b1.w};
            #pragma unroll
            for (int i = 0; i < 8; i++)
                #pragma unroll
                for (int j = 0; j < 8; j++)
                    acc[i][j] += av[i] * bv[j];
        }
    }
    #pragma unroll
    for (int i = 0; i < 8; i++) {
        int gm = bm + ty * 8 + i;
        if (gm < n) {
            g_xproj[(size_t)gm * 32 + tx] =
                make_float4(acc[i][0], acc[i][1], acc[i][2], acc[i][3]);
            g_xproj[(size_t)gm * 32 + 16 + tx] =
                make_float4(acc[i][4], acc[i][5], acc[i][6], acc[i][7]);
        }
    }
}

// ---------------- a_src / a_dst: warp per node ----------------
__global__ void k_attn(const float* __restrict__ att_src,
                       const float* __restrict__ att_dst, int n) {
    int warp = (blockIdx.x * blockDim.x + threadIdx.x) >> 5;
    int lane = threadIdx.x & 31;
    if (warp >= n) return;
    float4 xp = g_xproj[(size_t)warp * 32 + lane];
    float4 as = *(const float4*)(att_src + lane * 4);
    float4 ad = *(const float4*)(att_dst + lane * 4);
    float ds = xp.x * as.x + xp.y * as.y + xp.z * as.z + xp.w * as.w;
    float dd = xp.x * ad.x + xp.y * ad.y + xp.z * ad.z + xp.w * ad.w;
    #pragma unroll
    for (int m = 1; m <= 4; m <<= 1) {
        ds += __shfl_xor_sync(FULLM, ds, m);
        dd += __shfl_xor_sync(FULLM, dd, m);
    }
    if ((lane & 7) == 0) {
        int h = lane >> 3;
        ((float*)&g_asrc[warp])[h] = ds;
        ((float*)&g_adst[warp])[h] = dd;
    }
}

// ---------------- 3-stage chip-wide exclusive scan of g_deg ----------------
__global__ void k_scan1(int n) {
    __shared__ int s[256];
    int t = threadIdx.x;
    int i = blockIdx.x * 256 + t;
    int v = (i < n) ? g_deg[i] : 0;
    s[t] = v;
    __syncthreads();
    #pragma unroll
    for (int o = 128; o > 0; o >>= 1) {
        if (t < o) s[t] += s[t + o];
        __syncthreads();
    }
    if (t == 0) g_bsum[blockIdx.x] = s[0];
}

__global__ void k_scan2(int nb, int n) {
    __shared__ int s[512];
    int t = threadIdx.x;
    int v = (t < nb) ? g_bsum[t] : 0;
    s[t] = v;
    __syncthreads();
    #pragma unroll
    for (int o = 1; o < 512; o <<= 1) {
        int u = (t >= o) ? s[t - o] : 0;
        __syncthreads();
        s[t] += u;
        __syncthreads();
    }
    if (t < nb) g_boff[t] = s[t] - v;
    if (t == 511) g_off[n] = s[511];
}

__global__ void k_scan3(int n) {
    __shared__ int s[256];
    int t = threadIdx.x;
    int i = blockIdx.x * 256 + t;
    int v = (i < n) ? g_deg[i] : 0;
    s[t] = v;
    __syncthreads();
    #pragma unroll
    for (int o = 1; o < 256; o <<= 1) {
        int u = (t >= o) ? s[t - o] : 0;
        __syncthreads();
        s[t] += u;
        __syncthreads();
    }
    if (i < n) {
        int off = g_boff[blockIdx.x] + s[t] - v;
        g_off[i] = off;
        g_cursor[i] = off;
    }
}

// ---------------- fused escore + scatter: 32 edges/warp, chunk-pipelined ----------------
// Order per iteration: matvec(c) -> issue loads(c+1) -> scatter(c).
// Next chunk's 16 LDG.128 fly behind the scatter's gather/atomic/store chains.
__global__ __launch_bounds__(256) void k_scatf(const int* __restrict__ edge_index,
                                               const float* __restrict__ edge_attr, int E) {
    __shared__ float Ws2[KED * KH];
    __shared__ float bp[KH];
    __shared__ float4 sp[8][32];            // [warp][edge-in-chunk] p-vector
    int tid = threadIdx.x;
    Ws2[tid] = g_W2[tid];
    if (tid < KH) bp[tid] = 0.f;
    __syncthreads();

    int lane = tid & 31, wid = tid >> 5;
    int l8 = lane & 7, g8 = lane >> 3;

    float wr[8][4];
    #pragma unroll
    for (int j = 0; j < 8; j++)
        #pragma unroll
        for (int h = 0; h < 4; h++)
            wr[j][h] = Ws2[(l8 * 8 + j) * 4 + h];

    float s0 = 0.f, s1 = 0.f, s2 = 0.f, s3 = 0.f;
    int nchunks = (E + 31) >> 5;
    int cw = gridDim.x * 8;
    int c = blockIdx.x * 8 + wid;

    float4 va[8], vb[8];
    if (c < nchunks) {
        int e0 = c * 32;
        #pragma unroll
        for (int j = 0; j < 8; j++) {
            int e = e0 + j * 4 + g8;
            const float* ea = edge_attr + (size_t)(e < E ? e : 0) * KED + l8 * 8;
            va[j] = *(const float4*)ea;
            vb[j] = *(const float4*)(ea + 4);
        }
    }

    for (; c < nchunks; ) {
        int e0 = c * 32;
        // matvec on current chunk's registers -> sp
        #pragma unroll
        for (int j = 0; j < 8; j++) {
            float av[8] = {va[j].x, va[j].y, va[j].z, va[j].w,
                           vb[j].x, vb[j].y, vb[j].z, vb[j].w};
            float p0 = 0.f, p1 = 0.f, p2 = 0.f, p3 = 0.f;
            #pragma unroll
            for (int q = 0; q < 8; q++) {
                p0 += av[q] * wr[q][0];
                p1 += av[q] * wr[q][1];
                p2 += av[q] * wr[q][2];
                p3 += av[q] * wr[q][3];
            }
            #pragma unroll
            for (int m = 1; m <= 4; m <<= 1) {
                p0 += __shfl_xor_sync(FULLM, p0, m);
                p1 += __shfl_xor_sync(FULLM, p1, m);
                p2 += __shfl_xor_sync(FULLM, p2, m);
                p3 += __shfl_xor_sync(FULLM, p3, m);
            }
            if (l8 == 0) {
                sp[wid][j * 4 + g8] = make_float4(p0, p1, p2, p3);
                if (e0 + j * 4 + g8 < E) { s0 += p0; s1 += p1; s2 += p2; s3 += p3; }
            }
        }
        // issue next chunk's loads (in flight behind the scatter below)
        int cn = c + cw;
        if (cn < nchunks) {
            int en0 = cn * 32;
            #pragma unroll
            for (int j = 0; j < 8; j++) {
                int e = en0 + j * 4 + g8;
                const float* ea = edge_attr + (size_t)(e < E ? e : 0) * KED + l8 * 8;
                va[j] = *(const float4*)ea;
                vb[j] = *(const float4*)(ea + 4);
            }
        }
        __syncwarp();
        // scatter current chunk: one edge per lane (32 parallel chains)
        int e = e0 + lane;
        if (e < E) {
            float4 p = sp[wid][lane];
            int src = edge_index[e];
            int dst = edge_index[E + e];
            float4 as = g_asrc[src];
            int pos = atomicAdd(&g_cursor[dst], 1);
            g_ssrc[pos] = src;
            g_salpha[pos] = make_float4(as.x + p.x, as.y + p.y, as.z + p.z, as.w + p.w);
        }
        __syncwarp();
        c = cn;
    }
    #pragma unroll
    for (int m = 8; m <= 16; m <<= 1) {
        s0 += __shfl_xor_sync(FULLM, s0, m);
        s1 += __shfl_xor_sync(FULLM, s1, m);
        s2 += __shfl_xor_sync(FULLM, s2, m);
        s3 += __shfl_xor_sync(FULLM, s3, m);
    }
    if (lane == 0) {
        atomicAdd(&bp[0], s0);
        atomicAdd(&bp[1], s1);
        atomicAdd(&bp[2], s2);
        atomicAdd(&bp[3], s3);
    }
    __syncthreads();
    if (tid < KH) atomicAdd(&g_loopsum[tid], bp[tid]);
}

// ---------------- aggregation: warp per node, prefetched softmax + weighted sum ----------------
__global__ __launch_bounds__(256) void k_agg(const float* __restrict__ bias,
                                             float* __restrict__ out, int n, float invE) {
    int i = (blockIdx.x * blockDim.x + threadIdx.x) >> 5;
    int lane = threadIdx.x & 31;
    if (i >= n) return;

    int hl = lane >> 3;
    int sub = lane & 3;

    float adst_s = ((const float*)&g_adst[i])[sub];
    float asrc_s = ((const float*)&g_asrc[i])[sub];
    float lae_s  = g_loopsum[sub] * invE;
    float4 xpi = g_xproj[(size_t)i * 32 + lane];

    float4 acc = make_float4(0.f, 0.f, 0.f, 0.f);
    float dsum = 0.f;

    float vs = asrc_s + adst_s + lae_s;
    vs = vs > 0.f ? vs : 0.2f * vs;
    float ws = __expf(vs);
    if (lane < 4) dsum += ws;
    {
        float w = __shfl_sync(FULLM, ws, hl);
        acc.x += w * xpi.x; acc.y += w * xpi.y; acc.z += w * xpi.z; acc.w += w * xpi.w;
    }

    int beg = g_off[i], end = g_off[i + 1];
    const float* salpha_f = (const float*)g_salpha;

    float ca = 0.f; int cs = i;
    if (beg < end) {
        if (beg + (lane >> 2) < end) ca = salpha_f[(size_t)beg * 4 + lane];
        if (lane < 8 && beg + lane < end) cs = g_ssrc[beg + lane];
    }
    for (int base = beg; base < end; base += 8) {
        int nb = base + 8;
        float na = 0.f; int ns = i;
        if (nb < end) {
            if (nb + (lane >> 2) < end) na = salpha_f[(size_t)nb * 4 + lane];
            if (lane < 8 && nb + lane < end) ns = g_ssrc[nb + lane];
        }
        float w = 0.f;
        if (base + (lane >> 2) < end) {
            float a = ca + adst_s;
            a = a > 0.f ? a : 0.2f * a;
            w = __expf(a);
        }
        dsum += w;
        #pragma unroll
        for (int k = 0; k < 8; k++) {
            int s = __shfl_sync(FULLM, cs, k);
            float we = __shfl_sync(FULLM, w, k * 4 + hl);
            float4 xp = g_xproj[(size_t)s * 32 + lane];
            acc.x += we * xp.x; acc.y += we * xp.y;
            acc.z += we * xp.z; acc.w += we * xp.w;
        }
        ca = na; cs = ns;
    }
    #pragma unroll
    for (int m = 4; m <= 16; m <<= 1) dsum += __shfl_xor_sync(FULLM, dsum, m);
    float denom = __shfl_sync(FULLM, dsum, hl);
    float inv = 1.0f / denom;
    float4 b4 = *(const float4*)(bias + lane * 4);
    float4 o;
    o.x = acc.x * inv + b4.x;
    o.y = acc.y * inv + b4.y;
    o.z = acc.z * inv + b4.z;
    o.w = acc.w * inv + b4.w;
    *(float4*)(out + (size_t)i * KHC + lane * 4) = o;
}

// ---------------- launch ----------------
extern "C" void kernel_launch(void* const* d_in, const int* in_sizes, int n_in,
                              void* d_out, int out_size) {
    const float* x         = (const float*)d_in[0];
    const int*   edge_idx  = (const int*)d_in[1];
    const float* edge_attr = (const float*)d_in[2];
    const float* W         = (const float*)d_in[3];
    const float* att_src   = (const float*)d_in[4];
    const float* att_dst   = (const float*)d_in[5];
    const float* W_edge    = (const float*)d_in[6];
    const float* att_edge  = (const float*)d_in[7];
    const float* bias      = (const float*)d_in[8];
    float* out = (float*)d_out;

    int n = in_sizes[0] / KIN;       // 100000
    int E = in_sizes[1] / 2;         // 1600000
    int nblk = (n + 255) / 256;      // 391

    k_reset<<<nblk, 256>>>(n);
    k_hist<<<(E + 255) / 256, 256>>>(edge_idx, E);
    k_w2<<<1, 256>>>(W_edge, att_edge);
    k_gemm<<<(n + 127) / 128, 256>>>(x, W, n);       // #4 -> profiled (r14 exact)
    k_attn<<<(n + 7) / 8, 256>>>(att_src, att_dst, n);
    k_scan1<<<nblk, 256>>>(n);
    k_scan2<<<1, 512>>>(nblk, n);
    k_scan3<<<nblk, 256>>>(n);
    k_scatf<<<3072, 256>>>(edge_idx, edge_attr, E);
    k_agg<<<(n + 7) / 8, 256>>>(bias, out, n, 1.0f / (float)E);
}

// round 17
// speedup vs baseline: 1.1912x; 1.0460x over previous
#include <cuda_runtime.h>
#include <cuda_bf16.h>
#include <cstdint>

#define KN      100000
#define KE      1600000
#define KIN     256
#define KED     64
#define KH      4
#define KC      32
#define KHC     128

#define FULLM 0xFFFFFFFFu

// ---------------- scratch (static device globals; no allocation) ----------------
__device__ float4 g_xproj[KN * 32];        // [N][128]  (51.2 MB)
__device__ float4 g_asrc[KN];
__device__ float4 g_adst[KN];
__device__ float  g_W2[KED * KH];          // [64][4]
__device__ float  g_loopsum[KH];
__device__ int    g_deg[KN];
__device__ int    g_off[KN + 1];
__device__ int    g_cursor[KN];
__device__ int    g_bsum[512];
__device__ int    g_boff[512];
__device__ int    g_ssrc[KE];
__device__ float4 g_salpha[KE];            // (25.6 MB)

__device__ __forceinline__ uint32_t smem_u32(const void* p) {
    return (uint32_t)__cvta_generic_to_shared(p);
}
__device__ __forceinline__ void cp16(uint32_t dst, const void* src) {
    asm volatile("cp.async.cg.shared.global [%0], [%1], 16;\n" :: "r"(dst), "l"(src));
}
__device__ __forceinline__ void cp_commit() { asm volatile("cp.async.commit_group;\n"); }
__device__ __forceinline__ void cp_wait0() { asm volatile("cp.async.wait_group 0;\n"); }
__device__ __forceinline__ void cp_wait1() { asm volatile("cp.async.wait_group 1;\n"); }

// ---------------- reset ----------------
__global__ void k_reset(int n) {
    int i = blockIdx.x * blockDim.x + threadIdx.x;
    if (i < n) g_deg[i] = 0;
    if (i < KH) g_loopsum[i] = 0.f;
}

// ---------------- W2[d][h] = sum_c W_edge[d, h*32+c] * att_edge[h, c] ----------------
__global__ void k_w2(const float* __restrict__ W_edge, const float* __restrict__ att_edge) {
    int t = threadIdx.x;                 // 256 threads
    int d = t >> 2, h = t & 3;
    float s = 0.f;
    #pragma unroll 8
    for (int c = 0; c < KC; c++)
        s += W_edge[d * KHC + h * KC + c] * att_edge[h * KC + c];
    g_W2[d * KH + h] = s;
}

// ---------------- histogram of dst ----------------
__global__ void k_hist(const int* __restrict__ edge_index, int E) {
    int e = blockIdx.x * blockDim.x + threadIdx.x;
    if (e < E) atomicAdd(&g_deg[edge_index[E + e]], 1);
}

// ---------------- GEMM: r14 structure, W via cp.async (fewer regs) -> 2 CTAs/SM ----------------
__global__ __launch_bounds__(256, 2) void k_gemm(const float* __restrict__ x,
                                                 const float* __restrict__ W, int n) {
    __shared__ float Xs[2][16][128];
    __shared__ float Ws[2][16][128];
    int tid = threadIdx.x;
    int bm = blockIdx.x * 128;
    int tx = tid & 15;
    int ty = tid >> 4;

    float acc[8][8];
    #pragma unroll
    for (int i = 0; i < 8; i++)
        #pragma unroll
        for (int j = 0; j < 8; j++) acc[i][j] = 0.f;

    int xr = tid >> 2;
    int xk = (tid & 3) << 2;
    int wk = tid >> 5;
    int wn = (tid & 31) << 2;

    int gm0 = bm + xr;
    int gm1 = bm + xr + 64;
    const float* xrow0 = x + (size_t)(gm0 < n ? gm0 : 0) * KIN + xk;
    const float* xrow1 = x + (size_t)(gm1 < n ? gm1 : 0) * KIN + xk;
    bool v0 = gm0 < n, v1 = gm1 < n;
    const float* wrow0 = W + (size_t)wk * KHC + wn;
    const float* wrow1 = W + (size_t)(wk + 8) * KHC + wn;
    uint32_t ws0 = smem_u32(&Ws[0][wk][wn]);
    uint32_t ws1 = smem_u32(&Ws[0][wk + 8][wn]);
    const uint32_t WSTRIDE = (uint32_t)(16 * 128 * 4);   // bytes between stage buffers
    const float4 z4 = make_float4(0.f, 0.f, 0.f, 0.f);

    // prologue: W chunk 0 via cp.async, X chunk 0 via LDG
    cp16(ws0, wrow0);
    cp16(ws1, wrow1);
    cp_commit();
    float4 xv0 = v0 ? *(const float4*)(xrow0) : z4;
    float4 xv1 = v1 ? *(const float4*)(xrow1) : z4;

    #pragma unroll 1
    for (int c = 0; c < 16; c++) {
        int s = c & 1;
        Xs[s][xk + 0][xr] = xv0.x;
        Xs[s][xk + 1][xr] = xv0.y;
        Xs[s][xk + 2][xr] = xv0.z;
        Xs[s][xk + 3][xr] = xv0.w;
        Xs[s][xk + 0][xr + 64] = xv1.x;
        Xs[s][xk + 1][xr + 64] = xv1.y;
        Xs[s][xk + 2][xr + 64] = xv1.z;
        Xs[s][xk + 3][xr + 64] = xv1.w;
        if (c < 15) {
            int kb = (c + 1) * 16;
            uint32_t off = (uint32_t)((c + 1) & 1) * WSTRIDE;
            cp16(ws0 + off, wrow0 + (size_t)kb * KHC);
            cp16(ws1 + off, wrow1 + (size_t)kb * KHC);
            cp_commit();
            xv0 = v0 ? *(const float4*)(xrow0 + kb) : z4;
            xv1 = v1 ? *(const float4*)(xrow1 + kb) : z4;
            cp_wait1();            // W(c) complete, W(c+1) may be pending
        } else {
            cp_wait0();
        }
        __syncthreads();
        #pragma unroll
        for (int k = 0; k < 16; k++) {
            float4 a0 = *(const float4*)&Xs[s][k][ty * 8];
            float4 a1 = *(const float4*)&Xs[s][k][ty * 8 + 4];
            float4 b0 = *(const float4*)&Ws[s][k][tx * 4];
            float4 b1 = *(const float4*)&Ws[s][k][tx * 4 + 64];
            float av[8] = {a0.x, a0.y, a0.z, a0.w, a1.x, a1.y, a1.z, a1.w};
            float bv[8] = {b0.x, b0.y, b0.z, b0.w, b1.x, b1.y, b1.z, b1.w};
            #pragma unroll
            for (int i = 0; i < 8; i++)
                #pragma unroll
                for (int j = 0; j < 8; j++)
                    acc[i][j] += av[i] * bv[j];
        }
        __syncthreads();
    }
    #pragma unroll
    for (int i = 0; i < 8; i++) {
        int gm = bm + ty * 8 + i;
        if (gm < n) {
            g_xproj[(size_t)gm * 32 + tx] =
                make_float4(acc[i][0], acc[i][1], acc[i][2], acc[i][3]);
            g_xproj[(size_t)gm * 32 + 16 + tx] =
                make_float4(acc[i][4], acc[i][5], acc[i][6], acc[i][7]);
        }
    }
}

// ---------------- a_src / a_dst: warp per node ----------------
__global__ void k_attn(const float* __restrict__ att_src,
                       const float* __restrict__ att_dst, int n) {
    int warp = (blockIdx.x * blockDim.x + threadIdx.x) >> 5;
    int lane = threadIdx.x & 31;
    if (warp >= n) return;
    float4 xp = g_xproj[(size_t)warp * 32 + lane];
    float4 as = *(const float4*)(att_src + lane * 4);
    float4 ad = *(const float4*)(att_dst + lane * 4);
    float ds = xp.x * as.x + xp.y * as.y + xp.z * as.z + xp.w * as.w;
    float dd = xp.x * ad.x + xp.y * ad.y + xp.z * ad.z + xp.w * ad.w;
    #pragma unroll
    for (int m = 1; m <= 4; m <<= 1) {
        ds += __shfl_xor_sync(FULLM, ds, m);
        dd += __shfl_xor_sync(FULLM, dd, m);
    }
    if ((lane & 7) == 0) {
        int h = lane >> 3;
        ((float*)&g_asrc[warp])[h] = ds;
        ((float*)&g_adst[warp])[h] = dd;
    }
}

// ---------------- 3-stage chip-wide exclusive scan of g_deg ----------------
__global__ void k_scan1(int n) {
    __shared__ int s[256];
    int t = threadIdx.x;
    int i = blockIdx.x * 256 + t;
    int v = (i < n) ? g_deg[i] : 0;
    s[t] = v;
    __syncthreads();
    #pragma unroll
    for (int o = 128; o > 0; o >>= 1) {
        if (t < o) s[t] += s[t + o];
        __syncthreads();
    }
    if (t == 0) g_bsum[blockIdx.x] = s[0];
}

__global__ void k_scan2(int nb, int n) {
    __shared__ int s[512];
    int t = threadIdx.x;
    int v = (t < nb) ? g_bsum[t] : 0;
    s[t] = v;
    __syncthreads();
    #pragma unroll
    for (int o = 1; o < 512; o <<= 1) {
        int u = (t >= o) ? s[t - o] : 0;
        __syncthreads();
        s[t] += u;
        __syncthreads();
    }
    if (t < nb) g_boff[t] = s[t] - v;
    if (t == 511) g_off[n] = s[511];
}

__global__ void k_scan3(int n) {
    __shared__ int s[256];
    int t = threadIdx.x;
    int i = blockIdx.x * 256 + t;
    int v = (i < n) ? g_deg[i] : 0;
    s[t] = v;
    __syncthreads();
    #pragma unroll
    for (int o = 1; o < 256; o <<= 1) {
        int u = (t >= o) ? s[t - o] : 0;
        __syncthreads();
        s[t] += u;
        __syncthreads();
    }
    if (i < n) {
        int off = g_boff[blockIdx.x] + s[t] - v;
        g_off[i] = off;
        g_cursor[i] = off;
    }
}

// ---------------- fused escore + scatter: 32 edges/warp, chunk-pipelined ----------------
__global__ __launch_bounds__(256) void k_scatf(const int* __restrict__ edge_index,
                                               const float* __restrict__ edge_attr, int E) {
    __shared__ float Ws2[KED * KH];
    __shared__ float bp[KH];
    __shared__ float4 sp[8][32];            // [warp][edge-in-chunk] p-vector
    int tid = threadIdx.x;
    Ws2[tid] = g_W2[tid];
    if (tid < KH) bp[tid] = 0.f;
    __syncthreads();

    int lane = tid & 31, wid = tid >> 5;
    int l8 = lane & 7, g8 = lane >> 3;

    float wr[8][4];
    #pragma unroll
    for (int j = 0; j < 8; j++)
        #pragma unroll
        for (int h = 0; h < 4; h++)
            wr[j][h] = Ws2[(l8 * 8 + j) * 4 + h];

    float s0 = 0.f, s1 = 0.f, s2 = 0.f, s3 = 0.f;
    int nchunks = (E + 31) >> 5;
    int cw = gridDim.x * 8;
    int c = blockIdx.x * 8 + wid;

    float4 va[8], vb[8];
    if (c < nchunks) {
        int e0 = c * 32;
        #pragma unroll
        for (int j = 0; j < 8; j++) {
            int e = e0 + j * 4 + g8;
            const float* ea = edge_attr + (size_t)(e < E ? e : 0) * KED + l8 * 8;
            va[j] = *(const float4*)ea;
            vb[j] = *(const float4*)(ea + 4);
        }
    }

    for (; c < nchunks; ) {
        int e0 = c * 32;
        #pragma unroll
        for (int j = 0; j < 8; j++) {
            float av[8] = {va[j].x, va[j].y, va[j].z, va[j].w,
                           vb[j].x, vb[j].y, vb[j].z, vb[j].w};
            float p0 = 0.f, p1 = 0.f, p2 = 0.f, p3 = 0.f;
            #pragma unroll
            for (int q = 0; q < 8; q++) {
                p0 += av[q] * wr[q][0];
                p1 += av[q] * wr[q][1];
                p2 += av[q] * wr[q][2];
                p3 += av[q] * wr[q][3];
            }
            #pragma unroll
            for (int m = 1; m <= 4; m <<= 1) {
                p0 += __shfl_xor_sync(FULLM, p0, m);
                p1 += __shfl_xor_sync(FULLM, p1, m);
                p2 += __shfl_xor_sync(FULLM, p2, m);
                p3 += __shfl_xor_sync(FULLM, p3, m);
            }
            if (l8 == 0) {
                sp[wid][j * 4 + g8] = make_float4(p0, p1, p2, p3);
                if (e0 + j * 4 + g8 < E) { s0 += p0; s1 += p1; s2 += p2; s3 += p3; }
            }
        }
        int cn = c + cw;
        if (cn < nchunks) {
            int en0 = cn * 32;
            #pragma unroll
            for (int j = 0; j < 8; j++) {
                int e = en0 + j * 4 + g8;
                const float* ea = edge_attr + (size_t)(e < E ? e : 0) * KED + l8 * 8;
                va[j] = *(const float4*)ea;
                vb[j] = *(const float4*)(ea + 4);
            }
        }
        __syncwarp();
        int e = e0 + lane;
        if (e < E) {
            float4 p = sp[wid][lane];
            int src = edge_index[e];
            int dst = edge_index[E + e];
            float4 as = g_asrc[src];
            int pos = atomicAdd(&g_cursor[dst], 1);
            g_ssrc[pos] = src;
            g_salpha[pos] = make_float4(as.x + p.x, as.y + p.y, as.z + p.z, as.w + p.w);
        }
        __syncwarp();
        c = cn;
    }
    #pragma unroll
    for (int m = 8; m <= 16; m <<= 1) {
        s0 += __shfl_xor_sync(FULLM, s0, m);
        s1 += __shfl_xor_sync(FULLM, s1, m);
        s2 += __shfl_xor_sync(FULLM, s2, m);
        s3 += __shfl_xor_sync(FULLM, s3, m);
    }
    if (lane == 0) {
        atomicAdd(&bp[0], s0);
        atomicAdd(&bp[1], s1);
        atomicAdd(&bp[2], s2);
        atomicAdd(&bp[3], s3);
    }
    __syncthreads();
    if (tid < KH) atomicAdd(&g_loopsum[tid], bp[tid]);
}

// ---------------- aggregation: warp per node, prefetched softmax + weighted sum ----------------
__global__ __launch_bounds__(256) void k_agg(const float* __restrict__ bias,
                                             float* __restrict__ out, int n, float invE) {
    int i = (blockIdx.x * blockDim.x + threadIdx.x) >> 5;
    int lane = threadIdx.x & 31;
    if (i >= n) return;

    int hl = lane >> 3;
    int sub = lane & 3;

    float adst_s = ((const float*)&g_adst[i])[sub];
    float asrc_s = ((const float*)&g_asrc[i])[sub];
    float lae_s  = g_loopsum[sub] * invE;
    float4 xpi = g_xproj[(size_t)i * 32 + lane];

    float4 acc = make_float4(0.f, 0.f, 0.f, 0.f);
    float dsum = 0.f;

    float vs = asrc_s + adst_s + lae_s;
    vs = vs > 0.f ? vs : 0.2f * vs;
    float ws = __expf(vs);
    if (lane < 4) dsum += ws;
    {
        float w = __shfl_sync(FULLM, ws, hl);
        acc.x += w * xpi.x; acc.y += w * xpi.y; acc.z += w * xpi.z; acc.w += w * xpi.w;
    }

    int beg = g_off[i], end = g_off[i + 1];
    const float* salpha_f = (const float*)g_salpha;

    float ca = 0.f; int cs = i;
    if (beg < end) {
        if (beg + (lane >> 2) < end) ca = salpha_f[(size_t)beg * 4 + lane];
        if (lane < 8 && beg + lane < end) cs = g_ssrc[beg + lane];
    }
    for (int base = beg; base < end; base += 8) {
        int nb = base + 8;
        float na = 0.f; int ns = i;
        if (nb < end) {
            if (nb + (lane >> 2) < end) na = salpha_f[(size_t)nb * 4 + lane];
            if (lane < 8 && nb + lane < end) ns = g_ssrc[nb + lane];
        }
        float w = 0.f;
        if (base + (lane >> 2) < end) {
            float a = ca + adst_s;
            a = a > 0.f ? a : 0.2f * a;
            w = __expf(a);
        }
        dsum += w;
        #pragma unroll
        for (int k = 0; k < 8; k++) {
            int s = __shfl_sync(FULLM, cs, k);
            float we = __shfl_sync(FULLM, w, k * 4 + hl);
            float4 xp = g_xproj[(size_t)s * 32 + lane];
            acc.x += we * xp.x; acc.y += we * xp.y;
            acc.z += we * xp.z; acc.w += we * xp.w;
        }
        ca = na; cs = ns;
    }
    #pragma unroll
    for (int m = 4; m <= 16; m <<= 1) dsum += __shfl_xor_sync(FULLM, dsum, m);
    float denom = __shfl_sync(FULLM, dsum, hl);
    float inv = 1.0f / denom;
    float4 b4 = *(const float4*)(bias + lane * 4);
    float4 o;
    o.x = acc.x * inv + b4.x;
    o.y = acc.y * inv + b4.y;
    o.z = acc.z * inv + b4.z;
    o.w = acc.w * inv + b4.w;
    *(float4*)(out + (size_t)i * KHC + lane * 4) = o;
}

// ---------------- launch ----------------
extern "C" void kernel_launch(void* const* d_in, const int* in_sizes, int n_in,
                              void* d_out, int out_size) {
    const float* x         = (const float*)d_in[0];
    const int*   edge_idx  = (const int*)d_in[1];
    const float* edge_attr = (const float*)d_in[2];
    const float* W         = (const float*)d_in[3];
    const float* att_src   = (const float*)d_in[4];
    const float* att_dst   = (const float*)d_in[5];
    const float* W_edge    = (const float*)d_in[6];
    const float* att_edge  = (const float*)d_in[7];
    const float* bias      = (const float*)d_in[8];
    float* out = (float*)d_out;

    int n = in_sizes[0] / KIN;       // 100000
    int E = in_sizes[1] / 2;         // 1600000
    int nblk = (n + 255) / 256;      // 391

    k_reset<<<nblk, 256>>>(n);
    k_hist<<<(E + 255) / 256, 256>>>(edge_idx, E);
    k_w2<<<1, 256>>>(W_edge, att_edge);
    k_gemm<<<(n + 127) / 128, 256>>>(x, W, n);       // #4 -> profiled
    k_attn<<<(n + 7) / 8, 256>>>(att_src, att_dst, n);
    k_scan1<<<nblk, 256>>>(n);
    k_scan2<<<1, 512>>>(nblk, n);
    k_scan3<<<nblk, 256>>>(n);
    k_scatf<<<3072, 256>>>(edge_idx, edge_attr, E);
    k_agg<<<(n + 7) / 8, 256>>>(bias, out, n, 1.0f / (float)E);
}